// round 12
// baseline (speedup 1.0000x reference)
#include <cuda_runtime.h>
#include <cuda_fp16.h>
#include <math.h>

// Problem dims
#define BB 256
#define TT 512
#define HH 256
#define G3 768          // 3*H
#define INDIM 75
#define BT (BB*TT)      // 131072

// ---------------- scratch (device globals; no allocations allowed) ---------
__device__ float g_xg[(size_t)BB * TT * G3];     // input-gate preactivations (reused per layer)
__device__ float g_out0[(size_t)BB * TT * HH];   // layer-0 hidden states
__device__ float g_hT[BB * HH];                  // layer-1 final hidden state

__device__ __forceinline__ unsigned f2tf32(float v) {
    unsigned u;
    asm("cvt.rna.tf32.f32 %0, %1;" : "=r"(u) : "f"(v));
    return u;
}

__device__ __forceinline__ unsigned pack_h2(float x, float y) {
    __half2 h = __floats2half2_rn(x, y);
    return *(unsigned*)&h;
}

__device__ __forceinline__ void mma_tf32(float c[4], const unsigned a[4], unsigned b0, unsigned b1) {
    asm volatile(
        "mma.sync.aligned.m16n8k8.row.col.f32.tf32.tf32.f32 "
        "{%0,%1,%2,%3}, {%4,%5,%6,%7}, {%8,%9}, {%0,%1,%2,%3};"
        : "+f"(c[0]), "+f"(c[1]), "+f"(c[2]), "+f"(c[3])
        : "r"(a[0]), "r"(a[1]), "r"(a[2]), "r"(a[3]), "r"(b0), "r"(b1));
}

__device__ __forceinline__ void mma_f16(float c[4], const unsigned a[4], unsigned b0, unsigned b1) {
    asm volatile(
        "mma.sync.aligned.m16n8k16.row.col.f32.f16.f16.f32 "
        "{%0,%1,%2,%3}, {%4,%5,%6,%7}, {%8,%9}, {%0,%1,%2,%3};"
        : "+f"(c[0]), "+f"(c[1]), "+f"(c[2]), "+f"(c[3])
        : "r"(a[0]), "r"(a[1]), "r"(a[2]), "r"(a[3]), "r"(b0), "r"(b1));
}

__device__ __forceinline__ unsigned smem_u32(const void* p) {
    unsigned a;
    asm("{ .reg .u64 t; cvta.to.shared.u64 t, %1; cvt.u32.u64 %0, t; }" : "=r"(a) : "l"(p));
    return a;
}

__device__ __forceinline__ unsigned mapa_rank(unsigned addr, unsigned rank) {
    unsigned r;
    asm("mapa.shared::cluster.u32 %0, %1, %2;" : "=r"(r) : "r"(addr), "r"(rank));
    return r;
}

#define CLUSTER_SYNC() do {                                            \
    asm volatile("barrier.cluster.arrive.aligned;" ::: "memory");      \
    asm volatile("barrier.cluster.wait.aligned;" ::: "memory");        \
} while (0)

// ================= TF32 GEMM, vector loads + RNA convert (K=256) ===========
#define TBM 128
#define TBN 64
#define TBK 16
#define TPAD 20

__global__ __launch_bounds__(256) void tf32_gemm_v4_kernel(
    const float* __restrict__ A, const float* __restrict__ W,
    const float* __restrict__ bias, float* __restrict__ C,
    int M, int N, int K)
{
    __shared__ unsigned As[TBM * TPAD];
    __shared__ unsigned Bs[TBN * TPAD];

    const int tid = threadIdx.x;
    const int wid = tid >> 5, lane = tid & 31;
    const int g = lane >> 2, t = lane & 3;
    const int wm = wid & 3, wn = wid >> 2;
    const int m0 = blockIdx.y * TBM;
    const int n0 = blockIdx.x * TBN;

    float acc[2][4][4];
#pragma unroll
    for (int mt = 0; mt < 2; mt++)
#pragma unroll
        for (int nt = 0; nt < 4; nt++)
#pragma unroll
            for (int i = 0; i < 4; i++) acc[mt][nt][i] = 0.f;

    const int arow = tid >> 2;
    const int akq = (tid & 3) * 4;
    const int brow = tid >> 2;
    const int bkq = (tid & 3) * 4;

    float4 ra[2], rb;
    const int nk = K / TBK;

#pragma unroll
    for (int j = 0; j < 2; j++)
        ra[j] = __ldg((const float4*)&A[(size_t)(m0 + arow + j * 64) * K + akq]);
    rb = __ldg((const float4*)&W[(size_t)(n0 + brow) * K + bkq]);

    for (int kt = 0; kt < nk; kt++) {
#pragma unroll
        for (int j = 0; j < 2; j++) {
            uint4 u;
            u.x = f2tf32(ra[j].x); u.y = f2tf32(ra[j].y);
            u.z = f2tf32(ra[j].z); u.w = f2tf32(ra[j].w);
            *(uint4*)&As[(arow + j * 64) * TPAD + akq] = u;
        }
        {
            uint4 u;
            u.x = f2tf32(rb.x); u.y = f2tf32(rb.y);
            u.z = f2tf32(rb.z); u.w = f2tf32(rb.w);
            *(uint4*)&Bs[brow * TPAD + bkq] = u;
        }
        __syncthreads();

        if (kt + 1 < nk) {
            const int kb = (kt + 1) * TBK;
#pragma unroll
            for (int j = 0; j < 2; j++)
                ra[j] = __ldg((const float4*)&A[(size_t)(m0 + arow + j * 64) * K + kb + akq]);
            rb = __ldg((const float4*)&W[(size_t)(n0 + brow) * K + kb + bkq]);
        }

#pragma unroll
        for (int ks = 0; ks < 2; ks++) {
            const int k = ks * 8;
            unsigned af[2][4];
#pragma unroll
            for (int mt = 0; mt < 2; mt++) {
                int row = wm * 32 + mt * 16;
                af[mt][0] = As[(row + g) * TPAD + k + t];
                af[mt][1] = As[(row + g + 8) * TPAD + k + t];
                af[mt][2] = As[(row + g) * TPAD + k + t + 4];
                af[mt][3] = As[(row + g + 8) * TPAD + k + t + 4];
            }
#pragma unroll
            for (int nt = 0; nt < 4; nt++) {
                int col = wn * 32 + nt * 8;
                unsigned b0 = Bs[(col + g) * TPAD + k + t];
                unsigned b1 = Bs[(col + g) * TPAD + k + t + 4];
#pragma unroll
                for (int mt = 0; mt < 2; mt++) mma_tf32(acc[mt][nt], af[mt], b0, b1);
            }
        }
        __syncthreads();
    }

#pragma unroll
    for (int mt = 0; mt < 2; mt++) {
#pragma unroll
        for (int nt = 0; nt < 4; nt++) {
            int row = m0 + wm * 32 + mt * 16 + g;
            int col = n0 + wn * 32 + nt * 8 + 2 * t;
            float b0 = bias[col], b1 = bias[col + 1];
            C[(size_t)row * N + col]           = acc[mt][nt][0] + b0;
            C[(size_t)row * N + col + 1]       = acc[mt][nt][1] + b1;
            C[(size_t)(row + 8) * N + col]     = acc[mt][nt][2] + b0;
            C[(size_t)(row + 8) * N + col + 1] = acc[mt][nt][3] + b1;
        }
    }
}

// ================= TF32 GEMM, scalar guarded loads + RNA (K=75) ============
__global__ __launch_bounds__(256) void tf32_gemm_bias_kernel(
    const float* __restrict__ A, const float* __restrict__ W,
    const float* __restrict__ bias, float* __restrict__ C,
    int M, int N, int K)
{
    __shared__ unsigned As[TBM * TPAD];
    __shared__ unsigned Bs[TBN * TPAD];

    const int tid = threadIdx.x;
    const int wid = tid >> 5, lane = tid & 31;
    const int g = lane >> 2, t = lane & 3;
    const int wm = wid & 3, wn = wid >> 2;
    const int m0 = blockIdx.y * TBM;
    const int n0 = blockIdx.x * TBN;

    float acc[2][4][4];
#pragma unroll
    for (int mt = 0; mt < 2; mt++)
#pragma unroll
        for (int nt = 0; nt < 4; nt++)
#pragma unroll
            for (int i = 0; i < 4; i++) acc[mt][nt][i] = 0.f;

    const int am = tid >> 4;
    const int ak = tid & 15;
    const int bn = tid >> 2;
    const int bk4 = (tid & 3) * 4;

    float ra[8], rb[4];
    const int nk = (K + TBK - 1) / TBK;

    {
#pragma unroll
        for (int i = 0; i < 8; i++) {
            int m = am + i * 16;
            ra[i] = (ak < K) ? __ldg(&A[(size_t)(m0 + m) * K + ak]) : 0.f;
        }
#pragma unroll
        for (int i = 0; i < 4; i++) {
            int k = bk4 + i;
            rb[i] = (k < K) ? __ldg(&W[(size_t)(n0 + bn) * K + k]) : 0.f;
        }
    }

    for (int kt = 0; kt < nk; kt++) {
#pragma unroll
        for (int i = 0; i < 8; i++) As[(am + i * 16) * TPAD + ak] = f2tf32(ra[i]);
#pragma unroll
        for (int i = 0; i < 4; i++) Bs[bn * TPAD + bk4 + i] = f2tf32(rb[i]);
        __syncthreads();

        if (kt + 1 < nk) {
            const int kb = (kt + 1) * TBK;
#pragma unroll
            for (int i = 0; i < 8; i++) {
                int m = am + i * 16;
                ra[i] = (kb + ak < K) ? __ldg(&A[(size_t)(m0 + m) * K + kb + ak]) : 0.f;
            }
#pragma unroll
            for (int i = 0; i < 4; i++) {
                int k = kb + bk4 + i;
                rb[i] = (k < K) ? __ldg(&W[(size_t)(n0 + bn) * K + k]) : 0.f;
            }
        }

#pragma unroll
        for (int ks = 0; ks < 2; ks++) {
            const int k = ks * 8;
            unsigned af[2][4];
#pragma unroll
            for (int mt = 0; mt < 2; mt++) {
                int row = wm * 32 + mt * 16;
                af[mt][0] = As[(row + g) * TPAD + k + t];
                af[mt][1] = As[(row + g + 8) * TPAD + k + t];
                af[mt][2] = As[(row + g) * TPAD + k + t + 4];
                af[mt][3] = As[(row + g + 8) * TPAD + k + t + 4];
            }
#pragma unroll
            for (int nt = 0; nt < 4; nt++) {
                int col = wn * 32 + nt * 8;
                unsigned b0 = Bs[(col + g) * TPAD + k + t];
                unsigned b1 = Bs[(col + g) * TPAD + k + t + 4];
#pragma unroll
                for (int mt = 0; mt < 2; mt++) mma_tf32(acc[mt][nt], af[mt], b0, b1);
            }
        }
        __syncthreads();
    }

#pragma unroll
    for (int mt = 0; mt < 2; mt++) {
#pragma unroll
        for (int nt = 0; nt < 4; nt++) {
            int row = m0 + wm * 32 + mt * 16 + g;
            int col = n0 + wn * 32 + nt * 8 + 2 * t;
            float b0 = bias[col], b1 = bias[col + 1];
            C[(size_t)row * N + col]           = acc[mt][nt][0] + b0;
            C[(size_t)row * N + col + 1]       = acc[mt][nt][1] + b1;
            C[(size_t)(row + 8) * N + col]     = acc[mt][nt][2] + b0;
            C[(size_t)(row + 8) * N + col + 1] = acc[mt][nt][3] + b1;
        }
    }
}

// ---------------- fp32 GEMM (tiny FC) --------------------------------------
#define GBM 128
#define GBN 64
#define GBK 8
__global__ __launch_bounds__(256) void gemm_bias_kernel(
    const float* __restrict__ A, const float* __restrict__ W,
    const float* __restrict__ bias, float* __restrict__ C,
    int M, int N, int K)
{
    __shared__ float As[GBK][GBM];
    __shared__ float Bs[GBK][GBN + 4];

    int tid = threadIdx.x;
    int tx = tid & 15;
    int ty = tid >> 4;
    int m0 = blockIdx.x * GBM;
    int n0 = blockIdx.y * GBN;

    float acc[8][4];
#pragma unroll
    for (int i = 0; i < 8; i++)
#pragma unroll
        for (int j = 0; j < 4; j++) acc[i][j] = 0.f;

    for (int k0 = 0; k0 < K; k0 += GBK) {
#pragma unroll
        for (int i = 0; i < 4; i++) {
            int idx = tid + i * 256;
            int m = idx >> 3, kk = idx & 7;
            float v = (k0 + kk < K) ? A[(size_t)(m0 + m) * K + k0 + kk] : 0.f;
            As[kk][m] = v;
        }
#pragma unroll
        for (int i = 0; i < 2; i++) {
            int idx = tid + i * 256;
            int n = idx >> 3, kk = idx & 7;
            float v = (k0 + kk < K) ? W[(size_t)(n0 + n) * K + k0 + kk] : 0.f;
            Bs[kk][n] = v;
        }
        __syncthreads();
#pragma unroll
        for (int kk = 0; kk < GBK; kk++) {
            float a[8], b[4];
#pragma unroll
            for (int i = 0; i < 8; i++) a[i] = As[kk][ty * 8 + i];
#pragma unroll
            for (int j = 0; j < 4; j++) b[j] = Bs[kk][tx * 4 + j];
#pragma unroll
            for (int i = 0; i < 8; i++)
#pragma unroll
                for (int j = 0; j < 4; j++) acc[i][j] = fmaf(a[i], b[j], acc[i][j]);
        }
        __syncthreads();
    }

    float bb[4];
#pragma unroll
    for (int j = 0; j < 4; j++) bb[j] = bias[n0 + tx * 4 + j];
#pragma unroll
    for (int i = 0; i < 8; i++) {
        size_t row = (size_t)(m0 + ty * 8 + i) * N + n0 + tx * 4;
#pragma unroll
        for (int j = 0; j < 4; j++) C[row + j] = acc[i][j] + bb[j];
    }
}

// ---------------- cluster GRU recurrence, fp16 mma, CL=4, 12 warps ---------
// 32 clusters x 4 CTAs; CTA = 64 units (192 gate rows) x 8 batches.
// 12 warps, one 16-row m-tile each (64 frag regs; no spill), each tile's 16
// mma split into two 8-deep independent chains. Epilogue (threads 0..127):
// 4 units x 8 batches each, fast-exp gates, fp16 push to 4 ranks, fp32 carry.
#define CL 4
#define RT_THREADS 384
#define RT_GRID 128
#define HPW 132         // h row stride in 32-bit words
#define DSP 9           // Ds row stride (8 batches + 1)
#define H32P 65         // hs32 row stride (64 + 1)

__global__ __launch_bounds__(RT_THREADS, 1) __cluster_dims__(CL, 1, 1)
void gru_rec_cluster_kernel(
    const float* __restrict__ W_hh, const float* __restrict__ b_hh, int layer0)
{
    __shared__ unsigned hs16[2][8 * HPW];    // h (fp16x2) [b][k-pair], ping-pong
    __shared__ float    hs32[2][8 * H32P];   // own 64 units, exact fp32, ping-pong
    __shared__ float    Ds[192 * DSP];       // mma accums [gate-row][b]

    const int tid = threadIdx.x;
    const int wid = tid >> 5;             // 0..11
    const int lane = tid & 31;
    const int g = lane >> 2, t = lane & 3;

    unsigned rank;
    asm("mov.u32 %0, %%cluster_ctarank;" : "=r"(rank));
    const int bg = blockIdx.x >> 2;       // batch group 0..31
    const int j0 = (int)rank * 64;        // this CTA's unit base
    const int b0 = bg * 8;

    // ---- preload static A fragments (fp16), ONE 16-row tile per warp ----
    // gate = wid/4 (4 warps per gate, 16 rows each -> 64 rows per gate)
    const int wrow = (wid >> 2) * HH + j0 + (wid & 3) * 16;
    unsigned a[16][4];
#pragma unroll
    for (int ks = 0; ks < 16; ks++) {
        int k = ks * 16;
        const float* r0 = &W_hh[(size_t)(wrow + g) * HH + k];
        const float* r1 = &W_hh[(size_t)(wrow + g + 8) * HH + k];
        a[ks][0] = pack_h2(__ldg(&r0[2 * t]),     __ldg(&r0[2 * t + 1]));
        a[ks][1] = pack_h2(__ldg(&r1[2 * t]),     __ldg(&r1[2 * t + 1]));
        a[ks][2] = pack_h2(__ldg(&r0[2 * t + 8]), __ldg(&r0[2 * t + 9]));
        a[ks][3] = pack_h2(__ldg(&r1[2 * t + 8]), __ldg(&r1[2 * t + 9]));
    }

    // ---- epilogue assignment: threads 0..127, batch eb (0..7), units ju4*4..+3
    const int eb = (tid & 127) >> 4;      // 0..7
    const int ju4 = tid & 15;             // 0..15
    float bhr[4], bhz[4], bhn[4];
    if (tid < 128) {
#pragma unroll
        for (int i = 0; i < 4; i++) {
            int j = j0 + ju4 * 4 + i;
            bhr[i] = __ldg(&b_hh[j]);
            bhz[i] = __ldg(&b_hh[HH + j]);
            bhn[i] = __ldg(&b_hh[2 * HH + j]);
        }
    }

    // cluster-mapped destinations for the h push (word offset = j/2)
    unsigned dst[CL];
    unsigned buf_delta = 0;
    {
        unsigned l0 = smem_u32(&hs16[0][eb * HPW + (j0 >> 1) + ju4 * 2]);
        unsigned l1 = smem_u32(&hs16[1][eb * HPW + (j0 >> 1) + ju4 * 2]);
        buf_delta = l1 - l0;
#pragma unroll
        for (int r = 0; r < CL; r++) dst[r] = mapa_rank(l0, (unsigned)r);
    }

    // ---- init: zero both h buffers ----
    for (int idx = tid; idx < 8 * HPW; idx += RT_THREADS) {
        hs16[0][idx] = 0u;
        hs16[1][idx] = 0u;
    }
    for (int idx = tid; idx < 8 * H32P; idx += RT_THREADS) {
        hs32[0][idx] = 0.f;
        hs32[1][idx] = 0.f;
    }
    __syncthreads();
    CLUSTER_SYNC();

    for (int s = 0; s < TT; s++) {
        const int cur = s & 1;
        const int nxt = cur ^ 1;

        // ---- xg prefetch (hidden under mma) ----
        float4 xr4, xz4, xn4;
        if (tid < 128) {
            const float* xgp = &g_xg[((size_t)(b0 + eb) * TT + s) * G3 + j0 + ju4 * 4];
            xr4 = __ldcg((const float4*)&xgp[0]);
            xz4 = __ldcg((const float4*)&xgp[HH]);
            xn4 = __ldcg((const float4*)&xgp[2 * HH]);
        }

        // ---- fp16 tensor-core matmul: D[192 x 8] = W_slice @ h^T ----
        // two independent 8-deep accumulator chains per warp
        const unsigned* hb = hs16[cur];
        float ca[4] = {0.f, 0.f, 0.f, 0.f};
        float cb[4] = {0.f, 0.f, 0.f, 0.f};
#pragma unroll
        for (int ks = 0; ks < 8; ks++) {
            int w0 = ks * 8;
            int w1 = (ks + 8) * 8;
            mma_f16(ca, a[ks],     hb[g * HPW + w0 + t], hb[g * HPW + w0 + t + 4]);
            mma_f16(cb, a[ks + 8], hb[g * HPW + w1 + t], hb[g * HPW + w1 + t + 4]);
        }
        {
            int lr = wid * 16 + g;
            Ds[lr * DSP + 2 * t]           = ca[0] + cb[0];
            Ds[lr * DSP + 2 * t + 1]       = ca[1] + cb[1];
            Ds[(lr + 8) * DSP + 2 * t]     = ca[2] + cb[2];
            Ds[(lr + 8) * DSP + 2 * t + 1] = ca[3] + cb[3];
        }
        __syncthreads();

        // ---- gates + state update + cluster-wide h push (fp16) ----
        if (tid < 128) {
            float hnew[4];
#pragma unroll
            for (int i = 0; i < 4; i++) {
                int jl = ju4 * 4 + i;      // local unit 0..63
                float xr = (i == 0) ? xr4.x : (i == 1) ? xr4.y : (i == 2) ? xr4.z : xr4.w;
                float xz = (i == 0) ? xz4.x : (i == 1) ? xz4.y : (i == 2) ? xz4.z : xz4.w;
                float xn = (i == 0) ? xn4.x : (i == 1) ? xn4.y : (i == 2) ? xn4.z : xn4.w;
                float pr = Ds[jl * DSP + eb];
                float pz = Ds[(64 + jl) * DSP + eb];
                float pn = Ds[(128 + jl) * DSP + eb];
                float hp = hs32[cur][eb * H32P + jl];
                // fast-exp sigmoid / tanh (validated: rel_err unchanged)
                float er = __expf(-(xr + bhr[i] + pr));
                float ez = __expf(-(xz + bhz[i] + pz));
                float r = 1.f / (1.f + er);
                float z = 1.f / (1.f + ez);
                float e2 = __expf(2.f * (xn + r * (bhn[i] + pn)));
                float nn = 1.f - 2.f / (e2 + 1.f);
                hnew[i] = (1.f - z) * nn + z * hp;
            }
#pragma unroll
            for (int i = 0; i < 4; i++)
                hs32[nxt][eb * H32P + ju4 * 4 + i] = hnew[i];
            unsigned u0 = pack_h2(hnew[0], hnew[1]);
            unsigned u1 = pack_h2(hnew[2], hnew[3]);
            unsigned bofs = (nxt ? buf_delta : 0u);
#pragma unroll
            for (int r = 0; r < CL; r++) {
                asm volatile("st.shared::cluster.v2.b32 [%0], {%1,%2};"
                             :: "r"(dst[r] + bofs), "r"(u0), "r"(u1)
                             : "memory");
            }
            if (layer0) {
                float4 hv = make_float4(hnew[0], hnew[1], hnew[2], hnew[3]);
                *(float4*)&g_out0[((size_t)(b0 + eb) * TT + s) * HH + j0 + ju4 * 4] = hv;
            } else if (s == TT - 1) {
                float4 hv = make_float4(hnew[0], hnew[1], hnew[2], hnew[3]);
                *(float4*)&g_hT[(size_t)(b0 + eb) * HH + j0 + ju4 * 4] = hv;
            }
        }

        // ---- one cluster barrier per step (4-CTA domain) ----
        CLUSTER_SYNC();
    }
}

// ---------------------------------------------------------------------------
extern "C" void kernel_launch(void* const* d_in, const int* in_sizes, int n_in,
                              void* d_out, int out_size)
{
    const float* x     = (const float*)d_in[0];
    const float* W_ih0 = (const float*)d_in[1];
    const float* W_hh0 = (const float*)d_in[2];
    const float* b_ih0 = (const float*)d_in[3];
    const float* b_hh0 = (const float*)d_in[4];
    const float* W_ih1 = (const float*)d_in[5];
    const float* W_hh1 = (const float*)d_in[6];
    const float* b_ih1 = (const float*)d_in[7];
    const float* b_hh1 = (const float*)d_in[8];
    const float* fc_W  = (const float*)d_in[9];
    const float* fc_b  = (const float*)d_in[10];
    float* out = (float*)d_out;

    float *xg, *out0, *hT;
    cudaGetSymbolAddress((void**)&xg,   g_xg);
    cudaGetSymbolAddress((void**)&out0, g_out0);
    cudaGetSymbolAddress((void**)&hT,   g_hT);

    // layer 0 input preactivations: [BT,75] @ [768,75]^T (scalar tf32 GEMM, RNA)
    tf32_gemm_bias_kernel<<<dim3(G3 / TBN, BT / TBM), 256>>>(x, W_ih0, b_ih0, xg, BT, G3, INDIM);
    // layer 0 recurrence -> g_out0 (CL=4, 12 warps, fp16 mma)
    gru_rec_cluster_kernel<<<RT_GRID, RT_THREADS>>>(W_hh0, b_hh0, 1);
    // layer 1 input preactivations: [BT,256] @ [768,256]^T (v4 tf32 GEMM, RNA)
    tf32_gemm_v4_kernel<<<dim3(G3 / TBN, BT / TBM), 256>>>(out0, W_ih1, b_ih1, xg, BT, G3, HH);
    // layer 1 recurrence -> g_hT
    gru_rec_cluster_kernel<<<RT_GRID, RT_THREADS>>>(W_hh1, b_hh1, 0);
    // FC: [256,256] @ [256,256]^T + b (fp32, tiny)
    gemm_bias_kernel<<<dim3(BB / GBM, HH / GBN), 256>>>(hT, fc_W, fc_b, out, BB, HH, HH);
}

// round 13
// speedup vs baseline: 1.0217x; 1.0217x over previous
#include <cuda_runtime.h>
#include <cuda_fp16.h>
#include <math.h>

// Problem dims
#define BB 256
#define TT 512
#define HH 256
#define G3 768          // 3*H
#define INDIM 75
#define BT (BB*TT)      // 131072

// ---------------- scratch (device globals; no allocations allowed) ---------
__device__ float g_xg[(size_t)BB * TT * G3];     // input-gate preactivations (reused per layer)
__device__ float g_out0[(size_t)BB * TT * HH];   // layer-0 hidden states
__device__ float g_hT[BB * HH];                  // layer-1 final hidden state

__device__ __forceinline__ unsigned f2tf32(float v) {
    unsigned u;
    asm("cvt.rna.tf32.f32 %0, %1;" : "=r"(u) : "f"(v));
    return u;
}

__device__ __forceinline__ unsigned pack_h2(float x, float y) {
    __half2 h = __floats2half2_rn(x, y);
    return *(unsigned*)&h;
}

__device__ __forceinline__ void mma_tf32(float c[4], const unsigned a[4], unsigned b0, unsigned b1) {
    asm volatile(
        "mma.sync.aligned.m16n8k8.row.col.f32.tf32.tf32.f32 "
        "{%0,%1,%2,%3}, {%4,%5,%6,%7}, {%8,%9}, {%0,%1,%2,%3};"
        : "+f"(c[0]), "+f"(c[1]), "+f"(c[2]), "+f"(c[3])
        : "r"(a[0]), "r"(a[1]), "r"(a[2]), "r"(a[3]), "r"(b0), "r"(b1));
}

__device__ __forceinline__ void mma_f16(float c[4], const unsigned a[4], unsigned b0, unsigned b1) {
    asm volatile(
        "mma.sync.aligned.m16n8k16.row.col.f32.f16.f16.f32 "
        "{%0,%1,%2,%3}, {%4,%5,%6,%7}, {%8,%9}, {%0,%1,%2,%3};"
        : "+f"(c[0]), "+f"(c[1]), "+f"(c[2]), "+f"(c[3])
        : "r"(a[0]), "r"(a[1]), "r"(a[2]), "r"(a[3]), "r"(b0), "r"(b1));
}

__device__ __forceinline__ unsigned smem_u32(const void* p) {
    unsigned a;
    asm("{ .reg .u64 t; cvta.to.shared.u64 t, %1; cvt.u32.u64 %0, t; }" : "=r"(a) : "l"(p));
    return a;
}

__device__ __forceinline__ unsigned mapa_rank(unsigned addr, unsigned rank) {
    unsigned r;
    asm("mapa.shared::cluster.u32 %0, %1, %2;" : "=r"(r) : "r"(addr), "r"(rank));
    return r;
}

#define CLUSTER_SYNC() do {                                            \
    asm volatile("barrier.cluster.arrive.aligned;" ::: "memory");      \
    asm volatile("barrier.cluster.wait.aligned;" ::: "memory");        \
} while (0)

// ================= FP16 GEMM (K % 32 == 0; used for xg1, K=256) ============
// C[M,N] = A[M,K] @ W[N,K]^T + bias. BM=128, BN=64, BK=32 elements.
// 256 threads = 8 warps (4m x 2n), warp tile 32x32, fp32 accum.
#define FBM 128
#define FBN 64
#define FBK 32
#define FPAD 20   // row stride in 32-bit words (16 data + 4 pad); banks (20g+t)%32 distinct

__global__ __launch_bounds__(256) void f16_gemm_bias_kernel(
    const float* __restrict__ A, const float* __restrict__ W,
    const float* __restrict__ bias, float* __restrict__ C,
    int M, int N, int K)
{
    __shared__ unsigned As[FBM * FPAD];
    __shared__ unsigned Bs[FBN * FPAD];

    const int tid = threadIdx.x;
    const int wid = tid >> 5, lane = tid & 31;
    const int g = lane >> 2, t = lane & 3;
    const int wm = wid & 3, wn = wid >> 2;
    const int m0 = blockIdx.y * FBM;
    const int n0 = blockIdx.x * FBN;

    float acc[2][4][4];
#pragma unroll
    for (int mt = 0; mt < 2; mt++)
#pragma unroll
        for (int nt = 0; nt < 4; nt++)
#pragma unroll
            for (int i = 0; i < 4; i++) acc[mt][nt][i] = 0.f;

    // A: row = tid>>1 (0..127), 16 elements at colbase = (tid&1)*16
    const int arow = tid >> 1;
    const int acb = (tid & 1) * 16;
    // W: row = tid>>2 (0..63), 8 elements at colbase = (tid&3)*8
    const int brow = tid >> 2;
    const int bcb = (tid & 3) * 8;

    float4 ra[4], rb[2];
    const int nk = K / FBK;

    // prefetch tile 0
#pragma unroll
    for (int j = 0; j < 4; j++)
        ra[j] = __ldg((const float4*)&A[(size_t)(m0 + arow) * K + acb + j * 4]);
#pragma unroll
    for (int j = 0; j < 2; j++)
        rb[j] = __ldg((const float4*)&W[(size_t)(n0 + brow) * K + bcb + j * 4]);

    for (int kt = 0; kt < nk; kt++) {
        // convert to fp16x2 and store
#pragma unroll
        for (int j = 0; j < 4; j++) {
            As[arow * FPAD + (acb >> 1) + j * 2]     = pack_h2(ra[j].x, ra[j].y);
            As[arow * FPAD + (acb >> 1) + j * 2 + 1] = pack_h2(ra[j].z, ra[j].w);
        }
#pragma unroll
        for (int j = 0; j < 2; j++) {
            Bs[brow * FPAD + (bcb >> 1) + j * 2]     = pack_h2(rb[j].x, rb[j].y);
            Bs[brow * FPAD + (bcb >> 1) + j * 2 + 1] = pack_h2(rb[j].z, rb[j].w);
        }
        __syncthreads();

        // prefetch next tile
        if (kt + 1 < nk) {
            const int kb = (kt + 1) * FBK;
#pragma unroll
            for (int j = 0; j < 4; j++)
                ra[j] = __ldg((const float4*)&A[(size_t)(m0 + arow) * K + kb + acb + j * 4]);
#pragma unroll
            for (int j = 0; j < 2; j++)
                rb[j] = __ldg((const float4*)&W[(size_t)(n0 + brow) * K + kb + bcb + j * 4]);
        }

        // compute: 2 k-steps of k=16 (8 words each)
#pragma unroll
        for (int ks = 0; ks < 2; ks++) {
            const int kw = ks * 8;
            unsigned af[2][4];
#pragma unroll
            for (int mt = 0; mt < 2; mt++) {
                int row = wm * 32 + mt * 16;
                af[mt][0] = As[(row + g) * FPAD + kw + t];
                af[mt][1] = As[(row + g + 8) * FPAD + kw + t];
                af[mt][2] = As[(row + g) * FPAD + kw + t + 4];
                af[mt][3] = As[(row + g + 8) * FPAD + kw + t + 4];
            }
#pragma unroll
            for (int nt = 0; nt < 4; nt++) {
                int col = wn * 32 + nt * 8;
                unsigned b0 = Bs[(col + g) * FPAD + kw + t];
                unsigned b1 = Bs[(col + g) * FPAD + kw + t + 4];
#pragma unroll
                for (int mt = 0; mt < 2; mt++) mma_f16(acc[mt][nt], af[mt], b0, b1);
            }
        }
        __syncthreads();
    }

#pragma unroll
    for (int mt = 0; mt < 2; mt++) {
#pragma unroll
        for (int nt = 0; nt < 4; nt++) {
            int row = m0 + wm * 32 + mt * 16 + g;
            int col = n0 + wn * 32 + nt * 8 + 2 * t;
            float b0 = bias[col], b1 = bias[col + 1];
            C[(size_t)row * N + col]           = acc[mt][nt][0] + b0;
            C[(size_t)row * N + col + 1]       = acc[mt][nt][1] + b1;
            C[(size_t)(row + 8) * N + col]     = acc[mt][nt][2] + b0;
            C[(size_t)(row + 8) * N + col + 1] = acc[mt][nt][3] + b1;
        }
    }
}

// ================= TF32 GEMM, scalar guarded loads + RNA (K=75) ============
#define TBM 128
#define TBN 64
#define TBK 16
#define TPAD 20

__global__ __launch_bounds__(256) void tf32_gemm_bias_kernel(
    const float* __restrict__ A, const float* __restrict__ W,
    const float* __restrict__ bias, float* __restrict__ C,
    int M, int N, int K)
{
    __shared__ unsigned As[TBM * TPAD];
    __shared__ unsigned Bs[TBN * TPAD];

    const int tid = threadIdx.x;
    const int wid = tid >> 5, lane = tid & 31;
    const int g = lane >> 2, t = lane & 3;
    const int wm = wid & 3, wn = wid >> 2;
    const int m0 = blockIdx.y * TBM;
    const int n0 = blockIdx.x * TBN;

    float acc[2][4][4];
#pragma unroll
    for (int mt = 0; mt < 2; mt++)
#pragma unroll
        for (int nt = 0; nt < 4; nt++)
#pragma unroll
            for (int i = 0; i < 4; i++) acc[mt][nt][i] = 0.f;

    const int am = tid >> 4;
    const int ak = tid & 15;
    const int bn = tid >> 2;
    const int bk4 = (tid & 3) * 4;

    float ra[8], rb[4];
    const int nk = (K + TBK - 1) / TBK;

    {
#pragma unroll
        for (int i = 0; i < 8; i++) {
            int m = am + i * 16;
            ra[i] = (ak < K) ? __ldg(&A[(size_t)(m0 + m) * K + ak]) : 0.f;
        }
#pragma unroll
        for (int i = 0; i < 4; i++) {
            int k = bk4 + i;
            rb[i] = (k < K) ? __ldg(&W[(size_t)(n0 + bn) * K + k]) : 0.f;
        }
    }

    for (int kt = 0; kt < nk; kt++) {
#pragma unroll
        for (int i = 0; i < 8; i++) As[(am + i * 16) * TPAD + ak] = f2tf32(ra[i]);
#pragma unroll
        for (int i = 0; i < 4; i++) Bs[bn * TPAD + bk4 + i] = f2tf32(rb[i]);
        __syncthreads();

        if (kt + 1 < nk) {
            const int kb = (kt + 1) * TBK;
#pragma unroll
            for (int i = 0; i < 8; i++) {
                int m = am + i * 16;
                ra[i] = (kb + ak < K) ? __ldg(&A[(size_t)(m0 + m) * K + kb + ak]) : 0.f;
            }
#pragma unroll
            for (int i = 0; i < 4; i++) {
                int k = kb + bk4 + i;
                rb[i] = (k < K) ? __ldg(&W[(size_t)(n0 + bn) * K + k]) : 0.f;
            }
        }

#pragma unroll
        for (int ks = 0; ks < 2; ks++) {
            const int k = ks * 8;
            unsigned af[2][4];
#pragma unroll
            for (int mt = 0; mt < 2; mt++) {
                int row = wm * 32 + mt * 16;
                af[mt][0] = As[(row + g) * TPAD + k + t];
                af[mt][1] = As[(row + g + 8) * TPAD + k + t];
                af[mt][2] = As[(row + g) * TPAD + k + t + 4];
                af[mt][3] = As[(row + g + 8) * TPAD + k + t + 4];
            }
#pragma unroll
            for (int nt = 0; nt < 4; nt++) {
                int col = wn * 32 + nt * 8;
                unsigned b0 = Bs[(col + g) * TPAD + k + t];
                unsigned b1 = Bs[(col + g) * TPAD + k + t + 4];
#pragma unroll
                for (int mt = 0; mt < 2; mt++) mma_tf32(acc[mt][nt], af[mt], b0, b1);
            }
        }
        __syncthreads();
    }

#pragma unroll
    for (int mt = 0; mt < 2; mt++) {
#pragma unroll
        for (int nt = 0; nt < 4; nt++) {
            int row = m0 + wm * 32 + mt * 16 + g;
            int col = n0 + wn * 32 + nt * 8 + 2 * t;
            float b0 = bias[col], b1 = bias[col + 1];
            C[(size_t)row * N + col]           = acc[mt][nt][0] + b0;
            C[(size_t)row * N + col + 1]       = acc[mt][nt][1] + b1;
            C[(size_t)(row + 8) * N + col]     = acc[mt][nt][2] + b0;
            C[(size_t)(row + 8) * N + col + 1] = acc[mt][nt][3] + b1;
        }
    }
}

// ---------------- fp32 GEMM (tiny FC) --------------------------------------
#define GBM 128
#define GBN 64
#define GBK 8
__global__ __launch_bounds__(256) void gemm_bias_kernel(
    const float* __restrict__ A, const float* __restrict__ W,
    const float* __restrict__ bias, float* __restrict__ C,
    int M, int N, int K)
{
    __shared__ float As[GBK][GBM];
    __shared__ float Bs[GBK][GBN + 4];

    int tid = threadIdx.x;
    int tx = tid & 15;
    int ty = tid >> 4;
    int m0 = blockIdx.x * GBM;
    int n0 = blockIdx.y * GBN;

    float acc[8][4];
#pragma unroll
    for (int i = 0; i < 8; i++)
#pragma unroll
        for (int j = 0; j < 4; j++) acc[i][j] = 0.f;

    for (int k0 = 0; k0 < K; k0 += GBK) {
#pragma unroll
        for (int i = 0; i < 4; i++) {
            int idx = tid + i * 256;
            int m = idx >> 3, kk = idx & 7;
            float v = (k0 + kk < K) ? A[(size_t)(m0 + m) * K + k0 + kk] : 0.f;
            As[kk][m] = v;
        }
#pragma unroll
        for (int i = 0; i < 2; i++) {
            int idx = tid + i * 256;
            int n = idx >> 3, kk = idx & 7;
            float v = (k0 + kk < K) ? W[(size_t)(n0 + n) * K + k0 + kk] : 0.f;
            Bs[kk][n] = v;
        }
        __syncthreads();
#pragma unroll
        for (int kk = 0; kk < GBK; kk++) {
            float a[8], b[4];
#pragma unroll
            for (int i = 0; i < 8; i++) a[i] = As[kk][ty * 8 + i];
#pragma unroll
            for (int j = 0; j < 4; j++) b[j] = Bs[kk][tx * 4 + j];
#pragma unroll
            for (int i = 0; i < 8; i++)
#pragma unroll
                for (int j = 0; j < 4; j++) acc[i][j] = fmaf(a[i], b[j], acc[i][j]);
        }
        __syncthreads();
    }

    float bb[4];
#pragma unroll
    for (int j = 0; j < 4; j++) bb[j] = bias[n0 + tx * 4 + j];
#pragma unroll
    for (int i = 0; i < 8; i++) {
        size_t row = (size_t)(m0 + ty * 8 + i) * N + n0 + tx * 4;
#pragma unroll
        for (int j = 0; j < 4; j++) C[row + j] = acc[i][j] + bb[j];
    }
}

// ---------------- cluster GRU recurrence, fp16 mma, CL=4 (R11 + fast exp) --
// 32 clusters x 4 CTAs; CTA = 64 units (192 gate rows) x 8 batches.
// 6 warps, two 16-row m-tiles per warp (proven fastest shape, R11).
#define CL 4
#define RT_THREADS 192
#define RT_GRID 128
#define HPW 132         // h row stride in 32-bit words
#define DSP 9           // Ds row stride (8 batches + 1)
#define H32P 65         // hs32 row stride (64 + 1)

__global__ __launch_bounds__(RT_THREADS, 1) __cluster_dims__(CL, 1, 1)
void gru_rec_cluster_kernel(
    const float* __restrict__ W_hh, const float* __restrict__ b_hh, int layer0)
{
    __shared__ unsigned hs16[2][8 * HPW];    // h (fp16x2) [b][k-pair], ping-pong
    __shared__ float    hs32[2][8 * H32P];   // own 64 units, exact fp32, ping-pong
    __shared__ float    Ds[192 * DSP];       // mma accums [gate-row][b]

    const int tid = threadIdx.x;
    const int wid = tid >> 5;             // 0..5
    const int lane = tid & 31;
    const int g = lane >> 2, t = lane & 3;

    unsigned rank;
    asm("mov.u32 %0, %%cluster_ctarank;" : "=r"(rank));
    const int bg = blockIdx.x >> 2;       // batch group 0..31
    const int j0 = (int)rank * 64;        // this CTA's unit base
    const int b0 = bg * 8;

    // ---- preload static A fragments (fp16), two 16-row tiles per warp ----
    const int gate_w = wid >> 1;                        // 0..2
    const int wrow = gate_w * HH + j0 + (wid & 1) * 32; // 32-row block base
    unsigned a[2][16][4];
#pragma unroll
    for (int tile = 0; tile < 2; tile++) {
        int rbase = wrow + tile * 16;
#pragma unroll
        for (int ks = 0; ks < 16; ks++) {
            int k = ks * 16;
            const float* r0 = &W_hh[(size_t)(rbase + g) * HH + k];
            const float* r1 = &W_hh[(size_t)(rbase + g + 8) * HH + k];
            a[tile][ks][0] = pack_h2(__ldg(&r0[2 * t]),     __ldg(&r0[2 * t + 1]));
            a[tile][ks][1] = pack_h2(__ldg(&r1[2 * t]),     __ldg(&r1[2 * t + 1]));
            a[tile][ks][2] = pack_h2(__ldg(&r0[2 * t + 8]), __ldg(&r0[2 * t + 9]));
            a[tile][ks][3] = pack_h2(__ldg(&r1[2 * t + 8]), __ldg(&r1[2 * t + 9]));
        }
    }

    // ---- epilogue assignment: threads 0..127, batch eb (0..7), units ju4*4..+3
    const int eb = (tid & 127) >> 4;      // 0..7
    const int ju4 = tid & 15;             // 0..15
    float bhr[4], bhz[4], bhn[4];
    if (tid < 128) {
#pragma unroll
        for (int i = 0; i < 4; i++) {
            int j = j0 + ju4 * 4 + i;
            bhr[i] = __ldg(&b_hh[j]);
            bhz[i] = __ldg(&b_hh[HH + j]);
            bhn[i] = __ldg(&b_hh[2 * HH + j]);
        }
    }

    // cluster-mapped destinations for the h push (word offset = j/2)
    unsigned dst[CL];
    unsigned buf_delta = 0;
    {
        unsigned l0 = smem_u32(&hs16[0][eb * HPW + (j0 >> 1) + ju4 * 2]);
        unsigned l1 = smem_u32(&hs16[1][eb * HPW + (j0 >> 1) + ju4 * 2]);
        buf_delta = l1 - l0;
#pragma unroll
        for (int r = 0; r < CL; r++) dst[r] = mapa_rank(l0, (unsigned)r);
    }

    // ---- init: zero both h buffers ----
    for (int idx = tid; idx < 8 * HPW; idx += RT_THREADS) {
        hs16[0][idx] = 0u;
        hs16[1][idx] = 0u;
    }
    for (int idx = tid; idx < 8 * H32P; idx += RT_THREADS) {
        hs32[0][idx] = 0.f;
        hs32[1][idx] = 0.f;
    }
    __syncthreads();
    CLUSTER_SYNC();

    for (int s = 0; s < TT; s++) {
        const int cur = s & 1;
        const int nxt = cur ^ 1;

        // ---- xg prefetch (hidden under mma) ----
        float4 xr4, xz4, xn4;
        if (tid < 128) {
            const float* xgp = &g_xg[((size_t)(b0 + eb) * TT + s) * G3 + j0 + ju4 * 4];
            xr4 = __ldcg((const float4*)&xgp[0]);
            xz4 = __ldcg((const float4*)&xgp[HH]);
            xn4 = __ldcg((const float4*)&xgp[2 * HH]);
        }

        // ---- fp16 tensor-core matmul: D[192 x 8] = W_slice @ h^T ----
        const unsigned* hb = hs16[cur];
        float c0[4] = {0.f, 0.f, 0.f, 0.f};   // tile 0 rows
        float c1[4] = {0.f, 0.f, 0.f, 0.f};   // tile 1 rows
#pragma unroll
        for (int ks = 0; ks < 16; ks++) {
            int w = ks * 8;
            unsigned b00 = hb[g * HPW + w + t];
            unsigned b01 = hb[g * HPW + w + t + 4];
            mma_f16(c0, a[0][ks], b00, b01);
            mma_f16(c1, a[1][ks], b00, b01);
        }
        {
            int lr = wid * 32 + g;
            Ds[lr * DSP + 2 * t]            = c0[0];
            Ds[lr * DSP + 2 * t + 1]        = c0[1];
            Ds[(lr + 8) * DSP + 2 * t]      = c0[2];
            Ds[(lr + 8) * DSP + 2 * t + 1]  = c0[3];
            Ds[(lr + 16) * DSP + 2 * t]     = c1[0];
            Ds[(lr + 16) * DSP + 2 * t + 1] = c1[1];
            Ds[(lr + 24) * DSP + 2 * t]     = c1[2];
            Ds[(lr + 24) * DSP + 2 * t + 1] = c1[3];
        }
        __syncthreads();

        // ---- gates + state update + cluster-wide h push (fp16) ----
        if (tid < 128) {
            float hnew[4];
#pragma unroll
            for (int i = 0; i < 4; i++) {
                int jl = ju4 * 4 + i;      // local unit 0..63
                float xr = (i == 0) ? xr4.x : (i == 1) ? xr4.y : (i == 2) ? xr4.z : xr4.w;
                float xz = (i == 0) ? xz4.x : (i == 1) ? xz4.y : (i == 2) ? xz4.z : xz4.w;
                float xn = (i == 0) ? xn4.x : (i == 1) ? xn4.y : (i == 2) ? xn4.z : xn4.w;
                float pr = Ds[jl * DSP + eb];
                float pz = Ds[(64 + jl) * DSP + eb];
                float pn = Ds[(128 + jl) * DSP + eb];
                float hp = hs32[cur][eb * H32P + jl];
                // fast-exp sigmoid / tanh (validated: rel_err unchanged)
                float er = __expf(-(xr + bhr[i] + pr));
                float ez = __expf(-(xz + bhz[i] + pz));
                float r = 1.f / (1.f + er);
                float z = 1.f / (1.f + ez);
                float e2 = __expf(2.f * (xn + r * (bhn[i] + pn)));
                float nn = 1.f - 2.f / (e2 + 1.f);
                hnew[i] = (1.f - z) * nn + z * hp;
            }
#pragma unroll
            for (int i = 0; i < 4; i++)
                hs32[nxt][eb * H32P + ju4 * 4 + i] = hnew[i];
            unsigned u0 = pack_h2(hnew[0], hnew[1]);
            unsigned u1 = pack_h2(hnew[2], hnew[3]);
            unsigned bofs = (nxt ? buf_delta : 0u);
#pragma unroll
            for (int r = 0; r < CL; r++) {
                asm volatile("st.shared::cluster.v2.b32 [%0], {%1,%2};"
                             :: "r"(dst[r] + bofs), "r"(u0), "r"(u1)
                             : "memory");
            }
            if (layer0) {
                float4 hv = make_float4(hnew[0], hnew[1], hnew[2], hnew[3]);
                *(float4*)&g_out0[((size_t)(b0 + eb) * TT + s) * HH + j0 + ju4 * 4] = hv;
            } else if (s == TT - 1) {
                float4 hv = make_float4(hnew[0], hnew[1], hnew[2], hnew[3]);
                *(float4*)&g_hT[(size_t)(b0 + eb) * HH + j0 + ju4 * 4] = hv;
            }
        }

        // ---- one cluster barrier per step (4-CTA domain) ----
        CLUSTER_SYNC();
    }
}

// ---------------------------------------------------------------------------
extern "C" void kernel_launch(void* const* d_in, const int* in_sizes, int n_in,
                              void* d_out, int out_size)
{
    const float* x     = (const float*)d_in[0];
    const float* W_ih0 = (const float*)d_in[1];
    const float* W_hh0 = (const float*)d_in[2];
    const float* b_ih0 = (const float*)d_in[3];
    const float* b_hh0 = (const float*)d_in[4];
    const float* W_ih1 = (const float*)d_in[5];
    const float* W_hh1 = (const float*)d_in[6];
    const float* b_ih1 = (const float*)d_in[7];
    const float* b_hh1 = (const float*)d_in[8];
    const float* fc_W  = (const float*)d_in[9];
    const float* fc_b  = (const float*)d_in[10];
    float* out = (float*)d_out;

    float *xg, *out0, *hT;
    cudaGetSymbolAddress((void**)&xg,   g_xg);
    cudaGetSymbolAddress((void**)&out0, g_out0);
    cudaGetSymbolAddress((void**)&hT,   g_hT);

    // layer 0 input preactivations: [BT,75] @ [768,75]^T (scalar tf32 GEMM, RNA)
    tf32_gemm_bias_kernel<<<dim3(G3 / TBN, BT / TBM), 256>>>(x, W_ih0, b_ih0, xg, BT, G3, INDIM);
    // layer 0 recurrence -> g_out0 (CL=4, 6 warps, fp16 mma, fast-exp)
    gru_rec_cluster_kernel<<<RT_GRID, RT_THREADS>>>(W_hh0, b_hh0, 1);
    // layer 1 input preactivations: [BT,256] @ [768,256]^T (fp16 GEMM, BK=32)
    f16_gemm_bias_kernel<<<dim3(G3 / FBN, BT / FBM), 256>>>(out0, W_ih1, b_ih1, xg, BT, G3, HH);
    // layer 1 recurrence -> g_hT
    gru_rec_cluster_kernel<<<RT_GRID, RT_THREADS>>>(W_hh1, b_hh1, 0);
    // FC: [256,256] @ [256,256]^T + b (fp32, tiny)
    gemm_bias_kernel<<<dim3(BB / GBM, HH / GBN), 256>>>(hT, fc_W, fc_b, out, BB, HH, HH);
}

// round 15
// speedup vs baseline: 1.0697x; 1.0470x over previous
#include <cuda_runtime.h>
#include <cuda_fp16.h>
#include <math.h>

// Problem dims
#define BB 256
#define TT 512
#define HH 256
#define G3 768          // 3*H
#define INDIM 75
#define BT (BB*TT)      // 131072

// ---------------- scratch (device globals; no allocations allowed) ---------
__device__ float g_xg[(size_t)BB * TT * G3];     // input-gate preactivations (reused per layer)
__device__ float g_out0[(size_t)BB * TT * HH];   // layer-0 hidden states
__device__ float g_hT[BB * HH];                  // layer-1 final hidden state

__device__ __forceinline__ unsigned f2tf32(float v) {
    unsigned u;
    asm("cvt.rna.tf32.f32 %0, %1;" : "=r"(u) : "f"(v));
    return u;
}

__device__ __forceinline__ unsigned pack_h2(float x, float y) {
    __half2 h = __floats2half2_rn(x, y);
    return *(unsigned*)&h;
}

__device__ __forceinline__ void mma_tf32(float c[4], const unsigned a[4], unsigned b0, unsigned b1) {
    asm volatile(
        "mma.sync.aligned.m16n8k8.row.col.f32.tf32.tf32.f32 "
        "{%0,%1,%2,%3}, {%4,%5,%6,%7}, {%8,%9}, {%0,%1,%2,%3};"
        : "+f"(c[0]), "+f"(c[1]), "+f"(c[2]), "+f"(c[3])
        : "r"(a[0]), "r"(a[1]), "r"(a[2]), "r"(a[3]), "r"(b0), "r"(b1));
}

__device__ __forceinline__ void mma_f16(float c[4], const unsigned a[4], unsigned b0, unsigned b1) {
    asm volatile(
        "mma.sync.aligned.m16n8k16.row.col.f32.f16.f16.f32 "
        "{%0,%1,%2,%3}, {%4,%5,%6,%7}, {%8,%9}, {%0,%1,%2,%3};"
        : "+f"(c[0]), "+f"(c[1]), "+f"(c[2]), "+f"(c[3])
        : "r"(a[0]), "r"(a[1]), "r"(a[2]), "r"(a[3]), "r"(b0), "r"(b1));
}

__device__ __forceinline__ unsigned smem_u32(const void* p) {
    unsigned a;
    asm("{ .reg .u64 t; cvta.to.shared.u64 t, %1; cvt.u32.u64 %0, t; }" : "=r"(a) : "l"(p));
    return a;
}

__device__ __forceinline__ unsigned mapa_rank(unsigned addr, unsigned rank) {
    unsigned r;
    asm("mapa.shared::cluster.u32 %0, %1, %2;" : "=r"(r) : "r"(addr), "r"(rank));
    return r;
}

#define CLUSTER_SYNC() do {                                            \
    asm volatile("barrier.cluster.arrive.aligned;" ::: "memory");      \
    asm volatile("barrier.cluster.wait.aligned;" ::: "memory");        \
} while (0)

// ================= FP16 GEMM (K % 32 == 0; used for xg1, K=256) ============
#define FBM 128
#define FBN 64
#define FBK 32
#define FPAD 20

__global__ __launch_bounds__(256) void f16_gemm_bias_kernel(
    const float* __restrict__ A, const float* __restrict__ W,
    const float* __restrict__ bias, float* __restrict__ C,
    int M, int N, int K)
{
    __shared__ unsigned As[FBM * FPAD];
    __shared__ unsigned Bs[FBN * FPAD];

    const int tid = threadIdx.x;
    const int wid = tid >> 5, lane = tid & 31;
    const int g = lane >> 2, t = lane & 3;
    const int wm = wid & 3, wn = wid >> 2;
    const int m0 = blockIdx.y * FBM;
    const int n0 = blockIdx.x * FBN;

    float acc[2][4][4];
#pragma unroll
    for (int mt = 0; mt < 2; mt++)
#pragma unroll
        for (int nt = 0; nt < 4; nt++)
#pragma unroll
            for (int i = 0; i < 4; i++) acc[mt][nt][i] = 0.f;

    const int arow = tid >> 1;
    const int acb = (tid & 1) * 16;
    const int brow = tid >> 2;
    const int bcb = (tid & 3) * 8;

    float4 ra[4], rb[2];
    const int nk = K / FBK;

#pragma unroll
    for (int j = 0; j < 4; j++)
        ra[j] = __ldg((const float4*)&A[(size_t)(m0 + arow) * K + acb + j * 4]);
#pragma unroll
    for (int j = 0; j < 2; j++)
        rb[j] = __ldg((const float4*)&W[(size_t)(n0 + brow) * K + bcb + j * 4]);

    for (int kt = 0; kt < nk; kt++) {
#pragma unroll
        for (int j = 0; j < 4; j++) {
            As[arow * FPAD + (acb >> 1) + j * 2]     = pack_h2(ra[j].x, ra[j].y);
            As[arow * FPAD + (acb >> 1) + j * 2 + 1] = pack_h2(ra[j].z, ra[j].w);
        }
#pragma unroll
        for (int j = 0; j < 2; j++) {
            Bs[brow * FPAD + (bcb >> 1) + j * 2]     = pack_h2(rb[j].x, rb[j].y);
            Bs[brow * FPAD + (bcb >> 1) + j * 2 + 1] = pack_h2(rb[j].z, rb[j].w);
        }
        __syncthreads();

        if (kt + 1 < nk) {
            const int kb = (kt + 1) * FBK;
#pragma unroll
            for (int j = 0; j < 4; j++)
                ra[j] = __ldg((const float4*)&A[(size_t)(m0 + arow) * K + kb + acb + j * 4]);
#pragma unroll
            for (int j = 0; j < 2; j++)
                rb[j] = __ldg((const float4*)&W[(size_t)(n0 + brow) * K + kb + bcb + j * 4]);
        }

#pragma unroll
        for (int ks = 0; ks < 2; ks++) {
            const int kw = ks * 8;
            unsigned af[2][4];
#pragma unroll
            for (int mt = 0; mt < 2; mt++) {
                int row = wm * 32 + mt * 16;
                af[mt][0] = As[(row + g) * FPAD + kw + t];
                af[mt][1] = As[(row + g + 8) * FPAD + kw + t];
                af[mt][2] = As[(row + g) * FPAD + kw + t + 4];
                af[mt][3] = As[(row + g + 8) * FPAD + kw + t + 4];
            }
#pragma unroll
            for (int nt = 0; nt < 4; nt++) {
                int col = wn * 32 + nt * 8;
                unsigned b0 = Bs[(col + g) * FPAD + kw + t];
                unsigned b1 = Bs[(col + g) * FPAD + kw + t + 4];
#pragma unroll
                for (int mt = 0; mt < 2; mt++) mma_f16(acc[mt][nt], af[mt], b0, b1);
            }
        }
        __syncthreads();
    }

#pragma unroll
    for (int mt = 0; mt < 2; mt++) {
#pragma unroll
        for (int nt = 0; nt < 4; nt++) {
            int row = m0 + wm * 32 + mt * 16 + g;
            int col = n0 + wn * 32 + nt * 8 + 2 * t;
            float b0 = bias[col], b1 = bias[col + 1];
            C[(size_t)row * N + col]           = acc[mt][nt][0] + b0;
            C[(size_t)row * N + col + 1]       = acc[mt][nt][1] + b1;
            C[(size_t)(row + 8) * N + col]     = acc[mt][nt][2] + b0;
            C[(size_t)(row + 8) * N + col + 1] = acc[mt][nt][3] + b1;
        }
    }
}

// ================= TF32 GEMM, scalar guarded loads + RNA (K=75) ============
#define TBM 128
#define TBN 64
#define TBK 16
#define TPAD 20

__global__ __launch_bounds__(256) void tf32_gemm_bias_kernel(
    const float* __restrict__ A, const float* __restrict__ W,
    const float* __restrict__ bias, float* __restrict__ C,
    int M, int N, int K)
{
    __shared__ unsigned As[TBM * TPAD];
    __shared__ unsigned Bs[TBN * TPAD];

    const int tid = threadIdx.x;
    const int wid = tid >> 5, lane = tid & 31;
    const int g = lane >> 2, t = lane & 3;
    const int wm = wid & 3, wn = wid >> 2;
    const int m0 = blockIdx.y * TBM;
    const int n0 = blockIdx.x * TBN;

    float acc[2][4][4];
#pragma unroll
    for (int mt = 0; mt < 2; mt++)
#pragma unroll
        for (int nt = 0; nt < 4; nt++)
#pragma unroll
            for (int i = 0; i < 4; i++) acc[mt][nt][i] = 0.f;

    const int am = tid >> 4;
    const int ak = tid & 15;
    const int bn = tid >> 2;
    const int bk4 = (tid & 3) * 4;

    float ra[8], rb[4];
    const int nk = (K + TBK - 1) / TBK;

    {
#pragma unroll
        for (int i = 0; i < 8; i++) {
            int m = am + i * 16;
            ra[i] = (ak < K) ? __ldg(&A[(size_t)(m0 + m) * K + ak]) : 0.f;
        }
#pragma unroll
        for (int i = 0; i < 4; i++) {
            int k = bk4 + i;
            rb[i] = (k < K) ? __ldg(&W[(size_t)(n0 + bn) * K + k]) : 0.f;
        }
    }

    for (int kt = 0; kt < nk; kt++) {
#pragma unroll
        for (int i = 0; i < 8; i++) As[(am + i * 16) * TPAD + ak] = f2tf32(ra[i]);
#pragma unroll
        for (int i = 0; i < 4; i++) Bs[bn * TPAD + bk4 + i] = f2tf32(rb[i]);
        __syncthreads();

        if (kt + 1 < nk) {
            const int kb = (kt + 1) * TBK;
#pragma unroll
            for (int i = 0; i < 8; i++) {
                int m = am + i * 16;
                ra[i] = (kb + ak < K) ? __ldg(&A[(size_t)(m0 + m) * K + kb + ak]) : 0.f;
            }
#pragma unroll
            for (int i = 0; i < 4; i++) {
                int k = kb + bk4 + i;
                rb[i] = (k < K) ? __ldg(&W[(size_t)(n0 + bn) * K + k]) : 0.f;
            }
        }

#pragma unroll
        for (int ks = 0; ks < 2; ks++) {
            const int k = ks * 8;
            unsigned af[2][4];
#pragma unroll
            for (int mt = 0; mt < 2; mt++) {
                int row = wm * 32 + mt * 16;
                af[mt][0] = As[(row + g) * TPAD + k + t];
                af[mt][1] = As[(row + g + 8) * TPAD + k + t];
                af[mt][2] = As[(row + g) * TPAD + k + t + 4];
                af[mt][3] = As[(row + g + 8) * TPAD + k + t + 4];
            }
#pragma unroll
            for (int nt = 0; nt < 4; nt++) {
                int col = wn * 32 + nt * 8;
                unsigned b0 = Bs[(col + g) * TPAD + k + t];
                unsigned b1 = Bs[(col + g) * TPAD + k + t + 4];
#pragma unroll
                for (int mt = 0; mt < 2; mt++) mma_tf32(acc[mt][nt], af[mt], b0, b1);
            }
        }
        __syncthreads();
    }

#pragma unroll
    for (int mt = 0; mt < 2; mt++) {
#pragma unroll
        for (int nt = 0; nt < 4; nt++) {
            int row = m0 + wm * 32 + mt * 16 + g;
            int col = n0 + wn * 32 + nt * 8 + 2 * t;
            float b0 = bias[col], b1 = bias[col + 1];
            C[(size_t)row * N + col]           = acc[mt][nt][0] + b0;
            C[(size_t)row * N + col + 1]       = acc[mt][nt][1] + b1;
            C[(size_t)(row + 8) * N + col]     = acc[mt][nt][2] + b0;
            C[(size_t)(row + 8) * N + col + 1] = acc[mt][nt][3] + b1;
        }
    }
}

// ---------------- fp32 GEMM (tiny FC) --------------------------------------
#define GBM 128
#define GBN 64
#define GBK 8
__global__ __launch_bounds__(256) void gemm_bias_kernel(
    const float* __restrict__ A, const float* __restrict__ W,
    const float* __restrict__ bias, float* __restrict__ C,
    int M, int N, int K)
{
    __shared__ float As[GBK][GBM];
    __shared__ float Bs[GBK][GBN + 4];

    int tid = threadIdx.x;
    int tx = tid & 15;
    int ty = tid >> 4;
    int m0 = blockIdx.x * GBM;
    int n0 = blockIdx.y * GBN;

    float acc[8][4];
#pragma unroll
    for (int i = 0; i < 8; i++)
#pragma unroll
        for (int j = 0; j < 4; j++) acc[i][j] = 0.f;

    for (int k0 = 0; k0 < K; k0 += GBK) {
#pragma unroll
        for (int i = 0; i < 4; i++) {
            int idx = tid + i * 256;
            int m = idx >> 3, kk = idx & 7;
            float v = (k0 + kk < K) ? A[(size_t)(m0 + m) * K + k0 + kk] : 0.f;
            As[kk][m] = v;
        }
#pragma unroll
        for (int i = 0; i < 2; i++) {
            int idx = tid + i * 256;
            int n = idx >> 3, kk = idx & 7;
            float v = (k0 + kk < K) ? W[(size_t)(n0 + n) * K + k0 + kk] : 0.f;
            Bs[kk][n] = v;
        }
        __syncthreads();
#pragma unroll
        for (int kk = 0; kk < GBK; kk++) {
            float a[8], b[4];
#pragma unroll
            for (int i = 0; i < 8; i++) a[i] = As[kk][ty * 8 + i];
#pragma unroll
            for (int j = 0; j < 4; j++) b[j] = Bs[kk][tx * 4 + j];
#pragma unroll
            for (int i = 0; i < 8; i++)
#pragma unroll
                for (int j = 0; j < 4; j++) acc[i][j] = fmaf(a[i], b[j], acc[i][j]);
        }
        __syncthreads();
    }

    float bb[4];
#pragma unroll
    for (int j = 0; j < 4; j++) bb[j] = bias[n0 + tx * 4 + j];
#pragma unroll
    for (int i = 0; i < 8; i++) {
        size_t row = (size_t)(m0 + ty * 8 + i) * N + n0 + tx * 4;
#pragma unroll
        for (int j = 0; j < 4; j++) C[row + j] = acc[i][j] + bb[j];
    }
}

// ---------------- cluster GRU recurrence, fp16 mma, CL=4 (R11 verbatim) ----
// 32 clusters x 4 CTAs; CTA = 64 units (192 gate rows) x 8 batches.
// 6 warps, two 16-row m-tiles per warp. Precise expf/tanhf epilogue.
#define CL 4
#define RT_THREADS 192
#define RT_GRID 128
#define HPW 132         // h row stride in 32-bit words
#define DSP 9           // Ds row stride (8 batches + 1)
#define H32P 65         // hs32 row stride (64 + 1)

__global__ __launch_bounds__(RT_THREADS, 1) __cluster_dims__(CL, 1, 1)
void gru_rec_cluster_kernel(
    const float* __restrict__ W_hh, const float* __restrict__ b_hh, int layer0)
{
    __shared__ unsigned hs16[2][8 * HPW];    // h (fp16x2) [b][k-pair], ping-pong
    __shared__ float    hs32[2][8 * H32P];   // own 64 units, exact fp32, ping-pong
    __shared__ float    Ds[192 * DSP];       // mma accums [gate-row][b]

    const int tid = threadIdx.x;
    const int wid = tid >> 5;             // 0..5
    const int lane = tid & 31;
    const int g = lane >> 2, t = lane & 3;

    unsigned rank;
    asm("mov.u32 %0, %%cluster_ctarank;" : "=r"(rank));
    const int bg = blockIdx.x >> 2;       // batch group 0..31
    const int j0 = (int)rank * 64;        // this CTA's unit base
    const int b0 = bg * 8;

    // ---- preload static A fragments (fp16), two 16-row tiles per warp ----
    const int gate_w = wid >> 1;                        // 0..2
    const int wrow = gate_w * HH + j0 + (wid & 1) * 32; // 32-row block base
    unsigned a[2][16][4];
#pragma unroll
    for (int tile = 0; tile < 2; tile++) {
        int rbase = wrow + tile * 16;
#pragma unroll
        for (int ks = 0; ks < 16; ks++) {
            int k = ks * 16;
            const float* r0 = &W_hh[(size_t)(rbase + g) * HH + k];
            const float* r1 = &W_hh[(size_t)(rbase + g + 8) * HH + k];
            a[tile][ks][0] = pack_h2(__ldg(&r0[2 * t]),     __ldg(&r0[2 * t + 1]));
            a[tile][ks][1] = pack_h2(__ldg(&r1[2 * t]),     __ldg(&r1[2 * t + 1]));
            a[tile][ks][2] = pack_h2(__ldg(&r0[2 * t + 8]), __ldg(&r0[2 * t + 9]));
            a[tile][ks][3] = pack_h2(__ldg(&r1[2 * t + 8]), __ldg(&r1[2 * t + 9]));
        }
    }

    // ---- epilogue assignment: threads 0..127, batch eb (0..7), units ju4*4..+3
    const int eb = (tid & 127) >> 4;      // 0..7
    const int ju4 = tid & 15;             // 0..15
    float bhr[4], bhz[4], bhn[4];
    if (tid < 128) {
#pragma unroll
        for (int i = 0; i < 4; i++) {
            int j = j0 + ju4 * 4 + i;
            bhr[i] = __ldg(&b_hh[j]);
            bhz[i] = __ldg(&b_hh[HH + j]);
            bhn[i] = __ldg(&b_hh[2 * HH + j]);
        }
    }

    // cluster-mapped destinations for the h push (word offset = j/2)
    unsigned dst[CL];
    unsigned buf_delta = 0;
    {
        unsigned l0 = smem_u32(&hs16[0][eb * HPW + (j0 >> 1) + ju4 * 2]);
        unsigned l1 = smem_u32(&hs16[1][eb * HPW + (j0 >> 1) + ju4 * 2]);
        buf_delta = l1 - l0;
#pragma unroll
        for (int r = 0; r < CL; r++) dst[r] = mapa_rank(l0, (unsigned)r);
    }

    // ---- init: zero both h buffers ----
    for (int idx = tid; idx < 8 * HPW; idx += RT_THREADS) {
        hs16[0][idx] = 0u;
        hs16[1][idx] = 0u;
    }
    for (int idx = tid; idx < 8 * H32P; idx += RT_THREADS) {
        hs32[0][idx] = 0.f;
        hs32[1][idx] = 0.f;
    }
    __syncthreads();
    CLUSTER_SYNC();

    for (int s = 0; s < TT; s++) {
        const int cur = s & 1;
        const int nxt = cur ^ 1;

        // ---- xg prefetch (hidden under mma) ----
        float4 xr4, xz4, xn4;
        if (tid < 128) {
            const float* xgp = &g_xg[((size_t)(b0 + eb) * TT + s) * G3 + j0 + ju4 * 4];
            xr4 = __ldcg((const float4*)&xgp[0]);
            xz4 = __ldcg((const float4*)&xgp[HH]);
            xn4 = __ldcg((const float4*)&xgp[2 * HH]);
        }

        // ---- fp16 tensor-core matmul: D[192 x 8] = W_slice @ h^T ----
        const unsigned* hb = hs16[cur];
        float c0[4] = {0.f, 0.f, 0.f, 0.f};   // tile 0 rows
        float c1[4] = {0.f, 0.f, 0.f, 0.f};   // tile 1 rows
#pragma unroll
        for (int ks = 0; ks < 16; ks++) {
            int w = ks * 8;
            unsigned b00 = hb[g * HPW + w + t];
            unsigned b01 = hb[g * HPW + w + t + 4];
            mma_f16(c0, a[0][ks], b00, b01);
            mma_f16(c1, a[1][ks], b00, b01);
        }
        {
            int lr = wid * 32 + g;
            Ds[lr * DSP + 2 * t]            = c0[0];
            Ds[lr * DSP + 2 * t + 1]        = c0[1];
            Ds[(lr + 8) * DSP + 2 * t]      = c0[2];
            Ds[(lr + 8) * DSP + 2 * t + 1]  = c0[3];
            Ds[(lr + 16) * DSP + 2 * t]     = c1[0];
            Ds[(lr + 16) * DSP + 2 * t + 1] = c1[1];
            Ds[(lr + 24) * DSP + 2 * t]     = c1[2];
            Ds[(lr + 24) * DSP + 2 * t + 1] = c1[3];
        }
        __syncthreads();

        // ---- gates + state update + cluster-wide h push (fp16) ----
        if (tid < 128) {
            float hnew[4];
#pragma unroll
            for (int i = 0; i < 4; i++) {
                int jl = ju4 * 4 + i;      // local unit 0..63
                float xr = (i == 0) ? xr4.x : (i == 1) ? xr4.y : (i == 2) ? xr4.z : xr4.w;
                float xz = (i == 0) ? xz4.x : (i == 1) ? xz4.y : (i == 2) ? xz4.z : xz4.w;
                float xn = (i == 0) ? xn4.x : (i == 1) ? xn4.y : (i == 2) ? xn4.z : xn4.w;
                float pr = Ds[jl * DSP + eb];
                float pz = Ds[(64 + jl) * DSP + eb];
                float pn = Ds[(128 + jl) * DSP + eb];
                float hp = hs32[cur][eb * H32P + jl];
                float r = 1.f / (1.f + expf(-(xr + bhr[i] + pr)));
                float z = 1.f / (1.f + expf(-(xz + bhz[i] + pz)));
                float nn = tanhf(xn + r * (bhn[i] + pn));
                hnew[i] = (1.f - z) * nn + z * hp;
            }
#pragma unroll
            for (int i = 0; i < 4; i++)
                hs32[nxt][eb * H32P + ju4 * 4 + i] = hnew[i];
            unsigned u0 = pack_h2(hnew[0], hnew[1]);
            unsigned u1 = pack_h2(hnew[2], hnew[3]);
            unsigned bofs = (nxt ? buf_delta : 0u);
#pragma unroll
            for (int r = 0; r < CL; r++) {
                asm volatile("st.shared::cluster.v2.b32 [%0], {%1,%2};"
                             :: "r"(dst[r] + bofs), "r"(u0), "r"(u1)
                             : "memory");
            }
            if (layer0) {
                float4 hv = make_float4(hnew[0], hnew[1], hnew[2], hnew[3]);
                *(float4*)&g_out0[((size_t)(b0 + eb) * TT + s) * HH + j0 + ju4 * 4] = hv;
            } else if (s == TT - 1) {
                float4 hv = make_float4(hnew[0], hnew[1], hnew[2], hnew[3]);
                *(float4*)&g_hT[(size_t)(b0 + eb) * HH + j0 + ju4 * 4] = hv;
            }
        }

        // ---- one cluster barrier per step (4-CTA domain) ----
        CLUSTER_SYNC();
    }
}

// ---------------------------------------------------------------------------
extern "C" void kernel_launch(void* const* d_in, const int* in_sizes, int n_in,
                              void* d_out, int out_size)
{
    const float* x     = (const float*)d_in[0];
    const float* W_ih0 = (const float*)d_in[1];
    const float* W_hh0 = (const float*)d_in[2];
    const float* b_ih0 = (const float*)d_in[3];
    const float* b_hh0 = (const float*)d_in[4];
    const float* W_ih1 = (const float*)d_in[5];
    const float* W_hh1 = (const float*)d_in[6];
    const float* b_ih1 = (const float*)d_in[7];
    const float* b_hh1 = (const float*)d_in[8];
    const float* fc_W  = (const float*)d_in[9];
    const float* fc_b  = (const float*)d_in[10];
    float* out = (float*)d_out;

    float *xg, *out0, *hT;
    cudaGetSymbolAddress((void**)&xg,   g_xg);
    cudaGetSymbolAddress((void**)&out0, g_out0);
    cudaGetSymbolAddress((void**)&hT,   g_hT);

    // layer 0 input preactivations: [BT,75] @ [768,75]^T (scalar tf32 GEMM, RNA)
    tf32_gemm_bias_kernel<<<dim3(G3 / TBN, BT / TBM), 256>>>(x, W_ih0, b_ih0, xg, BT, G3, INDIM);
    // layer 0 recurrence -> g_out0 (CL=4, 6 warps, fp16 mma, precise exp)
    gru_rec_cluster_kernel<<<RT_GRID, RT_THREADS>>>(W_hh0, b_hh0, 1);
    // layer 1 input preactivations: [BT,256] @ [768,256]^T (fp16 GEMM, BK=32)
    f16_gemm_bias_kernel<<<dim3(G3 / FBN, BT / FBM), 256>>>(out0, W_ih1, b_ih1, xg, BT, G3, HH);
    // layer 1 recurrence -> g_hT
    gru_rec_cluster_kernel<<<RT_GRID, RT_THREADS>>>(W_hh1, b_hh1, 0);
    // FC: [256,256] @ [256,256]^T + b (fp32, tiny)
    gemm_bias_kernel<<<dim3(BB / GBM, HH / GBN), 256>>>(hT, fc_W, fc_b, out, BB, HH, HH);
}

// round 16
// speedup vs baseline: 1.1076x; 1.0354x over previous
#include <cuda_runtime.h>
#include <cuda_fp16.h>
#include <math.h>

// Problem dims
#define BB 256
#define TT 512
#define HH 256
#define G3 768          // 3*H
#define INDIM 75
#define BT (BB*TT)      // 131072

// ---------------- scratch (device globals; no allocations allowed) ---------
__device__ float g_xg[(size_t)BB * TT * G3];     // input-gate preactivations (reused per layer)
__device__ float g_out0[(size_t)BB * TT * HH];   // layer-0 hidden states
__device__ float g_hT[BB * HH];                  // layer-1 final hidden state

__device__ __forceinline__ unsigned f2tf32(float v) {
    unsigned u;
    asm("cvt.rna.tf32.f32 %0, %1;" : "=r"(u) : "f"(v));
    return u;
}

__device__ __forceinline__ unsigned pack_h2(float x, float y) {
    __half2 h = __floats2half2_rn(x, y);
    return *(unsigned*)&h;
}

__device__ __forceinline__ void mma_tf32(float c[4], const unsigned a[4], unsigned b0, unsigned b1) {
    asm volatile(
        "mma.sync.aligned.m16n8k8.row.col.f32.tf32.tf32.f32 "
        "{%0,%1,%2,%3}, {%4,%5,%6,%7}, {%8,%9}, {%0,%1,%2,%3};"
        : "+f"(c[0]), "+f"(c[1]), "+f"(c[2]), "+f"(c[3])
        : "r"(a[0]), "r"(a[1]), "r"(a[2]), "r"(a[3]), "r"(b0), "r"(b1));
}

__device__ __forceinline__ void mma_f16(float c[4], const unsigned a[4], unsigned b0, unsigned b1) {
    asm volatile(
        "mma.sync.aligned.m16n8k16.row.col.f32.f16.f16.f32 "
        "{%0,%1,%2,%3}, {%4,%5,%6,%7}, {%8,%9}, {%0,%1,%2,%3};"
        : "+f"(c[0]), "+f"(c[1]), "+f"(c[2]), "+f"(c[3])
        : "r"(a[0]), "r"(a[1]), "r"(a[2]), "r"(a[3]), "r"(b0), "r"(b1));
}

__device__ __forceinline__ unsigned smem_u32(const void* p) {
    unsigned a;
    asm("{ .reg .u64 t; cvta.to.shared.u64 t, %1; cvt.u32.u64 %0, t; }" : "=r"(a) : "l"(p));
    return a;
}

__device__ __forceinline__ unsigned mapa_rank(unsigned addr, unsigned rank) {
    unsigned r;
    asm("mapa.shared::cluster.u32 %0, %1, %2;" : "=r"(r) : "r"(addr), "r"(rank));
    return r;
}

#define CLUSTER_SYNC() do {                                            \
    asm volatile("barrier.cluster.arrive.aligned;" ::: "memory");      \
    asm volatile("barrier.cluster.wait.aligned;" ::: "memory");        \
} while (0)

// ================= FP16 GEMM v2 (K % 32 == 0; xg1, K=256) ==================
// C[M,N] = A[M,K] @ W[N,K]^T + bias. BM=128, BN=128, BK=32.
// 256 threads = 8 warps in 2(m) x 4(n); warp tile 64x32 -> 16 mma per 24 LDS.
#define FBM 128
#define FBN 128
#define FBK 32
#define FPAD 20   // row stride in 32-bit words (16 data + 4 pad)

__global__ __launch_bounds__(256) void f16_gemm_v2_kernel(
    const float* __restrict__ A, const float* __restrict__ W,
    const float* __restrict__ bias, float* __restrict__ C,
    int M, int N, int K)
{
    __shared__ unsigned As[FBM * FPAD];
    __shared__ unsigned Bs[FBN * FPAD];

    const int tid = threadIdx.x;
    const int wid = tid >> 5, lane = tid & 31;
    const int g = lane >> 2, t = lane & 3;
    const int wm = wid & 1, wn = wid >> 1;
    const int m0 = blockIdx.y * FBM;
    const int n0 = blockIdx.x * FBN;

    float acc[4][4][4];
#pragma unroll
    for (int mt = 0; mt < 4; mt++)
#pragma unroll
        for (int nt = 0; nt < 4; nt++)
#pragma unroll
            for (int i = 0; i < 4; i++) acc[mt][nt][i] = 0.f;

    // loaders: row = tid>>1 (0..127), 16 floats at (tid&1)*16
    const int lrow = tid >> 1;
    const int lcb = (tid & 1) * 16;
    const int nk = K / FBK;

    for (int kt = 0; kt < nk; kt++) {
        const int kb = kt * FBK;
        float4 va[4], vb[4];
#pragma unroll
        for (int j = 0; j < 4; j++) {
            va[j] = __ldg((const float4*)&A[(size_t)(m0 + lrow) * K + kb + lcb + j * 4]);
            vb[j] = __ldg((const float4*)&W[(size_t)(n0 + lrow) * K + kb + lcb + j * 4]);
        }
        if (kt > 0) __syncthreads();   // previous tile fully consumed
#pragma unroll
        for (int j = 0; j < 4; j++) {
            As[lrow * FPAD + (lcb >> 1) + j * 2]     = pack_h2(va[j].x, va[j].y);
            As[lrow * FPAD + (lcb >> 1) + j * 2 + 1] = pack_h2(va[j].z, va[j].w);
            Bs[lrow * FPAD + (lcb >> 1) + j * 2]     = pack_h2(vb[j].x, vb[j].y);
            Bs[lrow * FPAD + (lcb >> 1) + j * 2 + 1] = pack_h2(vb[j].z, vb[j].w);
        }
        __syncthreads();

#pragma unroll
        for (int ks = 0; ks < 2; ks++) {
            const int kw = ks * 8;
            unsigned af[4][4];
#pragma unroll
            for (int mt = 0; mt < 4; mt++) {
                int row = wm * 64 + mt * 16;
                af[mt][0] = As[(row + g) * FPAD + kw + t];
                af[mt][1] = As[(row + g + 8) * FPAD + kw + t];
                af[mt][2] = As[(row + g) * FPAD + kw + t + 4];
                af[mt][3] = As[(row + g + 8) * FPAD + kw + t + 4];
            }
#pragma unroll
            for (int nt = 0; nt < 4; nt++) {
                int col = wn * 32 + nt * 8;
                unsigned b0 = Bs[(col + g) * FPAD + kw + t];
                unsigned b1 = Bs[(col + g) * FPAD + kw + t + 4];
#pragma unroll
                for (int mt = 0; mt < 4; mt++) mma_f16(acc[mt][nt], af[mt], b0, b1);
            }
        }
    }

#pragma unroll
    for (int mt = 0; mt < 4; mt++) {
#pragma unroll
        for (int nt = 0; nt < 4; nt++) {
            int row = m0 + wm * 64 + mt * 16 + g;
            int col = n0 + wn * 32 + nt * 8 + 2 * t;
            float b0 = bias[col], b1 = bias[col + 1];
            C[(size_t)row * N + col]           = acc[mt][nt][0] + b0;
            C[(size_t)row * N + col + 1]       = acc[mt][nt][1] + b1;
            C[(size_t)(row + 8) * N + col]     = acc[mt][nt][2] + b0;
            C[(size_t)(row + 8) * N + col + 1] = acc[mt][nt][3] + b1;
        }
    }
}

// ================= TF32 GEMM, scalar guarded loads + RNA (K=75) ============
#define TBM 128
#define TBN 64
#define TBK 16
#define TPAD 20

__global__ __launch_bounds__(256) void tf32_gemm_bias_kernel(
    const float* __restrict__ A, const float* __restrict__ W,
    const float* __restrict__ bias, float* __restrict__ C,
    int M, int N, int K)
{
    __shared__ unsigned As[TBM * TPAD];
    __shared__ unsigned Bs[TBN * TPAD];

    const int tid = threadIdx.x;
    const int wid = tid >> 5, lane = tid & 31;
    const int g = lane >> 2, t = lane & 3;
    const int wm = wid & 3, wn = wid >> 2;
    const int m0 = blockIdx.y * TBM;
    const int n0 = blockIdx.x * TBN;

    float acc[2][4][4];
#pragma unroll
    for (int mt = 0; mt < 2; mt++)
#pragma unroll
        for (int nt = 0; nt < 4; nt++)
#pragma unroll
            for (int i = 0; i < 4; i++) acc[mt][nt][i] = 0.f;

    const int am = tid >> 4;
    const int ak = tid & 15;
    const int bn = tid >> 2;
    const int bk4 = (tid & 3) * 4;

    float ra[8], rb[4];
    const int nk = (K + TBK - 1) / TBK;

    {
#pragma unroll
        for (int i = 0; i < 8; i++) {
            int m = am + i * 16;
            ra[i] = (ak < K) ? __ldg(&A[(size_t)(m0 + m) * K + ak]) : 0.f;
        }
#pragma unroll
        for (int i = 0; i < 4; i++) {
            int k = bk4 + i;
            rb[i] = (k < K) ? __ldg(&W[(size_t)(n0 + bn) * K + k]) : 0.f;
        }
    }

    for (int kt = 0; kt < nk; kt++) {
#pragma unroll
        for (int i = 0; i < 8; i++) As[(am + i * 16) * TPAD + ak] = f2tf32(ra[i]);
#pragma unroll
        for (int i = 0; i < 4; i++) Bs[bn * TPAD + bk4 + i] = f2tf32(rb[i]);
        __syncthreads();

        if (kt + 1 < nk) {
            const int kb = (kt + 1) * TBK;
#pragma unroll
            for (int i = 0; i < 8; i++) {
                int m = am + i * 16;
                ra[i] = (kb + ak < K) ? __ldg(&A[(size_t)(m0 + m) * K + kb + ak]) : 0.f;
            }
#pragma unroll
            for (int i = 0; i < 4; i++) {
                int k = kb + bk4 + i;
                rb[i] = (k < K) ? __ldg(&W[(size_t)(n0 + bn) * K + k]) : 0.f;
            }
        }

#pragma unroll
        for (int ks = 0; ks < 2; ks++) {
            const int k = ks * 8;
            unsigned af[2][4];
#pragma unroll
            for (int mt = 0; mt < 2; mt++) {
                int row = wm * 32 + mt * 16;
                af[mt][0] = As[(row + g) * TPAD + k + t];
                af[mt][1] = As[(row + g + 8) * TPAD + k + t];
                af[mt][2] = As[(row + g) * TPAD + k + t + 4];
                af[mt][3] = As[(row + g + 8) * TPAD + k + t + 4];
            }
#pragma unroll
            for (int nt = 0; nt < 4; nt++) {
                int col = wn * 32 + nt * 8;
                unsigned b0 = Bs[(col + g) * TPAD + k + t];
                unsigned b1 = Bs[(col + g) * TPAD + k + t + 4];
#pragma unroll
                for (int mt = 0; mt < 2; mt++) mma_tf32(acc[mt][nt], af[mt], b0, b1);
            }
        }
        __syncthreads();
    }

#pragma unroll
    for (int mt = 0; mt < 2; mt++) {
#pragma unroll
        for (int nt = 0; nt < 4; nt++) {
            int row = m0 + wm * 32 + mt * 16 + g;
            int col = n0 + wn * 32 + nt * 8 + 2 * t;
            float b0 = bias[col], b1 = bias[col + 1];
            C[(size_t)row * N + col]           = acc[mt][nt][0] + b0;
            C[(size_t)row * N + col + 1]       = acc[mt][nt][1] + b1;
            C[(size_t)(row + 8) * N + col]     = acc[mt][nt][2] + b0;
            C[(size_t)(row + 8) * N + col + 1] = acc[mt][nt][3] + b1;
        }
    }
}

// ---------------- fp32 GEMM (tiny FC) --------------------------------------
#define GBM 128
#define GBN 64
#define GBK 8
__global__ __launch_bounds__(256) void gemm_bias_kernel(
    const float* __restrict__ A, const float* __restrict__ W,
    const float* __restrict__ bias, float* __restrict__ C,
    int M, int N, int K)
{
    __shared__ float As[GBK][GBM];
    __shared__ float Bs[GBK][GBN + 4];

    int tid = threadIdx.x;
    int tx = tid & 15;
    int ty = tid >> 4;
    int m0 = blockIdx.x * GBM;
    int n0 = blockIdx.y * GBN;

    float acc[8][4];
#pragma unroll
    for (int i = 0; i < 8; i++)
#pragma unroll
        for (int j = 0; j < 4; j++) acc[i][j] = 0.f;

    for (int k0 = 0; k0 < K; k0 += GBK) {
#pragma unroll
        for (int i = 0; i < 4; i++) {
            int idx = tid + i * 256;
            int m = idx >> 3, kk = idx & 7;
            float v = (k0 + kk < K) ? A[(size_t)(m0 + m) * K + k0 + kk] : 0.f;
            As[kk][m] = v;
        }
#pragma unroll
        for (int i = 0; i < 2; i++) {
            int idx = tid + i * 256;
            int n = idx >> 3, kk = idx & 7;
            float v = (k0 + kk < K) ? W[(size_t)(n0 + n) * K + k0 + kk] : 0.f;
            Bs[kk][n] = v;
        }
        __syncthreads();
#pragma unroll
        for (int kk = 0; kk < GBK; kk++) {
            float a[8], b[4];
#pragma unroll
            for (int i = 0; i < 8; i++) a[i] = As[kk][ty * 8 + i];
#pragma unroll
            for (int j = 0; j < 4; j++) b[j] = Bs[kk][tx * 4 + j];
#pragma unroll
            for (int i = 0; i < 8; i++)
#pragma unroll
                for (int j = 0; j < 4; j++) acc[i][j] = fmaf(a[i], b[j], acc[i][j]);
        }
        __syncthreads();
    }

    float bb[4];
#pragma unroll
    for (int j = 0; j < 4; j++) bb[j] = bias[n0 + tx * 4 + j];
#pragma unroll
    for (int i = 0; i < 8; i++) {
        size_t row = (size_t)(m0 + ty * 8 + i) * N + n0 + tx * 4;
#pragma unroll
        for (int j = 0; j < 4; j++) C[row + j] = acc[i][j] + bb[j];
    }
}

// ---------------- cluster GRU recurrence, fp16 mma, CL=4 (R11 verbatim) ----
// 32 clusters x 4 CTAs; CTA = 64 units (192 gate rows) x 8 batches.
// 6 warps, two 16-row m-tiles per warp. Precise expf/tanhf epilogue.
#define CL 4
#define RT_THREADS 192
#define RT_GRID 128
#define HPW 132         // h row stride in 32-bit words
#define DSP 9           // Ds row stride (8 batches + 1)
#define H32P 65         // hs32 row stride (64 + 1)

__global__ __launch_bounds__(RT_THREADS, 1) __cluster_dims__(CL, 1, 1)
void gru_rec_cluster_kernel(
    const float* __restrict__ W_hh, const float* __restrict__ b_hh, int layer0)
{
    __shared__ unsigned hs16[2][8 * HPW];    // h (fp16x2) [b][k-pair], ping-pong
    __shared__ float    hs32[2][8 * H32P];   // own 64 units, exact fp32, ping-pong
    __shared__ float    Ds[192 * DSP];       // mma accums [gate-row][b]

    const int tid = threadIdx.x;
    const int wid = tid >> 5;             // 0..5
    const int lane = tid & 31;
    const int g = lane >> 2, t = lane & 3;

    unsigned rank;
    asm("mov.u32 %0, %%cluster_ctarank;" : "=r"(rank));
    const int bg = blockIdx.x >> 2;       // batch group 0..31
    const int j0 = (int)rank * 64;        // this CTA's unit base
    const int b0 = bg * 8;

    // ---- preload static A fragments (fp16), two 16-row tiles per warp ----
    const int gate_w = wid >> 1;                        // 0..2
    const int wrow = gate_w * HH + j0 + (wid & 1) * 32; // 32-row block base
    unsigned a[2][16][4];
#pragma unroll
    for (int tile = 0; tile < 2; tile++) {
        int rbase = wrow + tile * 16;
#pragma unroll
        for (int ks = 0; ks < 16; ks++) {
            int k = ks * 16;
            const float* r0 = &W_hh[(size_t)(rbase + g) * HH + k];
            const float* r1 = &W_hh[(size_t)(rbase + g + 8) * HH + k];
            a[tile][ks][0] = pack_h2(__ldg(&r0[2 * t]),     __ldg(&r0[2 * t + 1]));
            a[tile][ks][1] = pack_h2(__ldg(&r1[2 * t]),     __ldg(&r1[2 * t + 1]));
            a[tile][ks][2] = pack_h2(__ldg(&r0[2 * t + 8]), __ldg(&r0[2 * t + 9]));
            a[tile][ks][3] = pack_h2(__ldg(&r1[2 * t + 8]), __ldg(&r1[2 * t + 9]));
        }
    }

    // ---- epilogue assignment: threads 0..127, batch eb (0..7), units ju4*4..+3
    const int eb = (tid & 127) >> 4;      // 0..7
    const int ju4 = tid & 15;             // 0..15
    float bhr[4], bhz[4], bhn[4];
    if (tid < 128) {
#pragma unroll
        for (int i = 0; i < 4; i++) {
            int j = j0 + ju4 * 4 + i;
            bhr[i] = __ldg(&b_hh[j]);
            bhz[i] = __ldg(&b_hh[HH + j]);
            bhn[i] = __ldg(&b_hh[2 * HH + j]);
        }
    }

    // cluster-mapped destinations for the h push (word offset = j/2)
    unsigned dst[CL];
    unsigned buf_delta = 0;
    {
        unsigned l0 = smem_u32(&hs16[0][eb * HPW + (j0 >> 1) + ju4 * 2]);
        unsigned l1 = smem_u32(&hs16[1][eb * HPW + (j0 >> 1) + ju4 * 2]);
        buf_delta = l1 - l0;
#pragma unroll
        for (int r = 0; r < CL; r++) dst[r] = mapa_rank(l0, (unsigned)r);
    }

    // ---- init: zero both h buffers ----
    for (int idx = tid; idx < 8 * HPW; idx += RT_THREADS) {
        hs16[0][idx] = 0u;
        hs16[1][idx] = 0u;
    }
    for (int idx = tid; idx < 8 * H32P; idx += RT_THREADS) {
        hs32[0][idx] = 0.f;
        hs32[1][idx] = 0.f;
    }
    __syncthreads();
    CLUSTER_SYNC();

    for (int s = 0; s < TT; s++) {
        const int cur = s & 1;
        const int nxt = cur ^ 1;

        // ---- xg prefetch (hidden under mma) ----
        float4 xr4, xz4, xn4;
        if (tid < 128) {
            const float* xgp = &g_xg[((size_t)(b0 + eb) * TT + s) * G3 + j0 + ju4 * 4];
            xr4 = __ldcg((const float4*)&xgp[0]);
            xz4 = __ldcg((const float4*)&xgp[HH]);
            xn4 = __ldcg((const float4*)&xgp[2 * HH]);
        }

        // ---- fp16 tensor-core matmul: D[192 x 8] = W_slice @ h^T ----
        const unsigned* hb = hs16[cur];
        float c0[4] = {0.f, 0.f, 0.f, 0.f};   // tile 0 rows
        float c1[4] = {0.f, 0.f, 0.f, 0.f};   // tile 1 rows
#pragma unroll
        for (int ks = 0; ks < 16; ks++) {
            int w = ks * 8;
            unsigned b00 = hb[g * HPW + w + t];
            unsigned b01 = hb[g * HPW + w + t + 4];
            mma_f16(c0, a[0][ks], b00, b01);
            mma_f16(c1, a[1][ks], b00, b01);
        }
        {
            int lr = wid * 32 + g;
            Ds[lr * DSP + 2 * t]            = c0[0];
            Ds[lr * DSP + 2 * t + 1]        = c0[1];
            Ds[(lr + 8) * DSP + 2 * t]      = c0[2];
            Ds[(lr + 8) * DSP + 2 * t + 1]  = c0[3];
            Ds[(lr + 16) * DSP + 2 * t]     = c1[0];
            Ds[(lr + 16) * DSP + 2 * t + 1] = c1[1];
            Ds[(lr + 24) * DSP + 2 * t]     = c1[2];
            Ds[(lr + 24) * DSP + 2 * t + 1] = c1[3];
        }
        __syncthreads();

        // ---- gates + state update + cluster-wide h push (fp16) ----
        if (tid < 128) {
            float hnew[4];
#pragma unroll
            for (int i = 0; i < 4; i++) {
                int jl = ju4 * 4 + i;      // local unit 0..63
                float xr = (i == 0) ? xr4.x : (i == 1) ? xr4.y : (i == 2) ? xr4.z : xr4.w;
                float xz = (i == 0) ? xz4.x : (i == 1) ? xz4.y : (i == 2) ? xz4.z : xz4.w;
                float xn = (i == 0) ? xn4.x : (i == 1) ? xn4.y : (i == 2) ? xn4.z : xn4.w;
                float pr = Ds[jl * DSP + eb];
                float pz = Ds[(64 + jl) * DSP + eb];
                float pn = Ds[(128 + jl) * DSP + eb];
                float hp = hs32[cur][eb * H32P + jl];
                float r = 1.f / (1.f + expf(-(xr + bhr[i] + pr)));
                float z = 1.f / (1.f + expf(-(xz + bhz[i] + pz)));
                float nn = tanhf(xn + r * (bhn[i] + pn));
                hnew[i] = (1.f - z) * nn + z * hp;
            }
#pragma unroll
            for (int i = 0; i < 4; i++)
                hs32[nxt][eb * H32P + ju4 * 4 + i] = hnew[i];
            unsigned u0 = pack_h2(hnew[0], hnew[1]);
            unsigned u1 = pack_h2(hnew[2], hnew[3]);
            unsigned bofs = (nxt ? buf_delta : 0u);
#pragma unroll
            for (int r = 0; r < CL; r++) {
                asm volatile("st.shared::cluster.v2.b32 [%0], {%1,%2};"
                             :: "r"(dst[r] + bofs), "r"(u0), "r"(u1)
                             : "memory");
            }
            if (layer0) {
                float4 hv = make_float4(hnew[0], hnew[1], hnew[2], hnew[3]);
                *(float4*)&g_out0[((size_t)(b0 + eb) * TT + s) * HH + j0 + ju4 * 4] = hv;
            } else if (s == TT - 1) {
                float4 hv = make_float4(hnew[0], hnew[1], hnew[2], hnew[3]);
                *(float4*)&g_hT[(size_t)(b0 + eb) * HH + j0 + ju4 * 4] = hv;
            }
        }

        // ---- one cluster barrier per step (4-CTA domain) ----
        CLUSTER_SYNC();
    }
}

// ---------------------------------------------------------------------------
extern "C" void kernel_launch(void* const* d_in, const int* in_sizes, int n_in,
                              void* d_out, int out_size)
{
    const float* x     = (const float*)d_in[0];
    const float* W_ih0 = (const float*)d_in[1];
    const float* W_hh0 = (const float*)d_in[2];
    const float* b_ih0 = (const float*)d_in[3];
    const float* b_hh0 = (const float*)d_in[4];
    const float* W_ih1 = (const float*)d_in[5];
    const float* W_hh1 = (const float*)d_in[6];
    const float* b_ih1 = (const float*)d_in[7];
    const float* b_hh1 = (const float*)d_in[8];
    const float* fc_W  = (const float*)d_in[9];
    const float* fc_b  = (const float*)d_in[10];
    float* out = (float*)d_out;

    float *xg, *out0, *hT;
    cudaGetSymbolAddress((void**)&xg,   g_xg);
    cudaGetSymbolAddress((void**)&out0, g_out0);
    cudaGetSymbolAddress((void**)&hT,   g_hT);

    // layer 0 input preactivations: [BT,75] @ [768,75]^T (scalar tf32 GEMM, RNA)
    tf32_gemm_bias_kernel<<<dim3(G3 / TBN, BT / TBM), 256>>>(x, W_ih0, b_ih0, xg, BT, G3, INDIM);
    // layer 0 recurrence -> g_out0 (CL=4, 6 warps, fp16 mma, precise exp)
    gru_rec_cluster_kernel<<<RT_GRID, RT_THREADS>>>(W_hh0, b_hh0, 1);
    // layer 1 input preactivations: [BT,256] @ [768,256]^T (fp16 GEMM v2, 128x128)
    f16_gemm_v2_kernel<<<dim3(G3 / FBN, BT / FBM), 256>>>(out0, W_ih1, b_ih1, xg, BT, G3, HH);
    // layer 1 recurrence -> g_hT
    gru_rec_cluster_kernel<<<RT_GRID, RT_THREADS>>>(W_hh1, b_hh1, 0);
    // FC: [256,256] @ [256,256]^T + b (fp32, tiny)
    gemm_bias_kernel<<<dim3(BB / GBM, HH / GBN), 256>>>(hT, fc_W, fc_b, out, BB, HH, HH);
}